// round 7
// baseline (speedup 1.0000x reference)
#include <cuda_runtime.h>
#include <math.h>

#define DIMK 64
#define NN 16
#define BATCH 4096
#define NRELS 33
#define NT 256
#define NITEMS 4
#define GRID (BATCH / NITEMS)

struct PerItem {
    float xbuf[NN * DIMK];    // 4 KB
    float userv[DIMK];
    float x0[DIMK];
    float x1[DIMK];
    float outf[DIMK];
    float attn[NN * NN];      // 1 KB
    float urel[NRELS + 3];
    float attn0[NN];
    int   e1[NN];
    int   e2[NN * NN];        // 1 KB
    int   r2[NN * NN];        // 1 KB
    int   r1[NN];
};

struct Smem {
    PerItem pi[NITEMS];
    float b0[DIMK];
    float b1[DIMK];
};

__device__ __forceinline__ float fsigmoid(float x) {
    return __fdividef(1.0f, 1.0f + __expf(-x));
}

__global__ __launch_bounds__(NT, 6)
void kgnn_kernel(const int* __restrict__ u, const int* __restrict__ v,
                 const int* __restrict__ adj, const int* __restrict__ rel_adj,
                 const float* __restrict__ usr_emb, const float* __restrict__ ent_emb,
                 const float* __restrict__ rel_emb,
                 const float* __restrict__ W0g, const float* __restrict__ b0g,
                 const float* __restrict__ W1g, const float* __restrict__ b1g,
                 float* __restrict__ out)
{
    extern __shared__ char smem_raw[];
    Smem& s = *reinterpret_cast<Smem*>(smem_raw);
    const int tid  = threadIdx.x;
    const int lane = tid & 31;
    const int warp = tid >> 5;
    const int c     = warp * 8 + (lane & 7);  // output column 0..63
    const int kh    = lane >> 3;              // k-quarter 0..3
    const int kbase = kh * 16;
    const bool kh0  = (kh == 0);

    const float4* ent4 = reinterpret_cast<const float4*>(ent_emb);
    const int item0 = blockIdx.x * NITEMS;

    // W0 column-slice in registers, once per CTA
    float Wreg[16];
    #pragma unroll
    for (int kk = 0; kk < 16; ++kk)
        Wreg[kk] = __ldg(W0g + (kbase + kk) * DIMK + c);
    if (tid < DIMK) { s.b0[tid] = b0g[tid]; s.b1[tid] = b1g[tid]; }
    __syncthreads();

    // ---- P1: indices + root vectors + urel (all items) ----
    #pragma unroll
    for (int ii = 0; ii < NITEMS; ++ii) {
        PerItem& p = s.pi[ii];
        const int vv = __ldg(v + item0 + ii);
        const int uu = __ldg(u + item0 + ii);
        const int m = tid >> 4, n = tid & 15;
        const int e1m = __ldg(adj + vv * NN + m);
        p.e2[tid] = __ldg(adj + e1m * NN + n);
        p.r2[tid] = __ldg(rel_adj + e1m * NN + n);
        if (n == 0) p.e1[m] = e1m;
        if (tid < 16) {
            p.r1[tid] = __ldg(rel_adj + vv * NN + tid);
            reinterpret_cast<float4*>(p.userv)[tid] = __ldg(
                reinterpret_cast<const float4*>(usr_emb) + uu * 16 + tid);
        }
        const float ua = __ldg(usr_emb + uu * DIMK + lane);
        const float ub = __ldg(usr_emb + uu * DIMK + lane + 32);
        for (int r = warp; r < NRELS; r += 8) {
            float pp = ua * __ldg(rel_emb + r * DIMK + lane)
                     + ub * __ldg(rel_emb + r * DIMK + lane + 32);
            #pragma unroll
            for (int off = 16; off > 0; off >>= 1)
                pp += __shfl_xor_sync(0xffffffffu, pp, off);
            if (lane == 0) p.urel[r] = pp;
        }
    }
    __syncthreads();

    // ---- P2: softmax via half-warp butterflies (all items) ----
    #pragma unroll
    for (int ii = 0; ii < NITEMS; ++ii) {
        PerItem& p = s.pi[ii];
        float sc = p.urel[p.r2[tid]];
        float mx = sc;
        #pragma unroll
        for (int off = 8; off > 0; off >>= 1)
            mx = fmaxf(mx, __shfl_xor_sync(0xffffffffu, mx, off));
        float e = __expf(sc - mx);
        float sum = e;
        #pragma unroll
        for (int off = 8; off > 0; off >>= 1)
            sum += __shfl_xor_sync(0xffffffffu, sum, off);
        p.attn[tid] = __fdividef(e, sum);

        if (warp == ii) {   // hop-0 softmax on warp ii
            float sc0 = p.urel[p.r1[lane & 15]];
            float m0 = sc0;
            #pragma unroll
            for (int off = 8; off > 0; off >>= 1)
                m0 = fmaxf(m0, __shfl_xor_sync(0xffffffffu, m0, off));
            float e0 = __expf(sc0 - m0);
            float s0 = e0;
            #pragma unroll
            for (int off = 8; off > 0; off >>= 1)
                s0 += __shfl_xor_sync(0xffffffffu, s0, off);
            if (lane < 16) p.attn0[lane] = __fdividef(e0, s0);
        }
    }
    __syncthreads();

    // ---- P3: hop-1 aggregation (all items) + x0 on warps 4..7 ----
    #pragma unroll
    for (int ii = 0; ii < NITEMS; ++ii) {
        PerItem& p = s.pi[ii];
        const int m  = warp * 2 + (lane >> 4);
        const int l4 = lane & 15;
        const int4*   e2v = reinterpret_cast<const int4*>(p.e2 + m * NN);
        const float4* av  = reinterpret_cast<const float4*>(p.attn + m * NN);
        float4 acc = __ldg(ent4 + p.e1[m] * 16 + l4);   // self vector
        #pragma unroll
        for (int j = 0; j < 4; ++j) {
            const int4   ei = e2v[j];
            const float4 aw = av[j];
            const float4 v0 = __ldg(ent4 + ei.x * 16 + l4);
            const float4 v1 = __ldg(ent4 + ei.y * 16 + l4);
            const float4 v2 = __ldg(ent4 + ei.z * 16 + l4);
            const float4 v3 = __ldg(ent4 + ei.w * 16 + l4);
            acc.x = fmaf(aw.x, v0.x, acc.x); acc.y = fmaf(aw.x, v0.y, acc.y);
            acc.z = fmaf(aw.x, v0.z, acc.z); acc.w = fmaf(aw.x, v0.w, acc.w);
            acc.x = fmaf(aw.y, v1.x, acc.x); acc.y = fmaf(aw.y, v1.y, acc.y);
            acc.z = fmaf(aw.y, v1.z, acc.z); acc.w = fmaf(aw.y, v1.w, acc.w);
            acc.x = fmaf(aw.z, v2.x, acc.x); acc.y = fmaf(aw.z, v2.y, acc.y);
            acc.z = fmaf(aw.z, v2.z, acc.z); acc.w = fmaf(aw.z, v2.w, acc.w);
            acc.x = fmaf(aw.w, v3.x, acc.x); acc.y = fmaf(aw.w, v3.y, acc.y);
            acc.z = fmaf(aw.w, v3.z, acc.z); acc.w = fmaf(aw.w, v3.w, acc.w);
        }
        reinterpret_cast<float4*>(p.xbuf + m * DIMK)[l4] = acc;

        if (warp == 4 + ii && lane < 16) {   // x0 aggregation, one warp per item
            const int vv = __ldg(v + item0 + ii);
            float4 a0 = __ldg(ent4 + vv * 16 + lane);
            #pragma unroll
            for (int n = 0; n < NN; ++n) {
                const float4 ev = __ldg(ent4 + p.e1[n] * 16 + lane);
                const float  an = p.attn0[n];
                a0.x = fmaf(an, ev.x, a0.x);
                a0.y = fmaf(an, ev.y, a0.y);
                a0.z = fmaf(an, ev.z, a0.z);
                a0.w = fmaf(an, ev.w, a0.w);
            }
            reinterpret_cast<float4*>(p.x0)[lane] = a0;
        }
    }
    __syncthreads();

    // ---- P4: fused GEMM (all items; h1 stays in registers) ----
    #pragma unroll
    for (int ii = 0; ii < NITEMS; ++ii) {
        PerItem& p = s.pi[ii];
        const float b0c = s.b0[c];
        float x1acc = 0.f;
        #pragma unroll
        for (int r = 0; r < NN; r += 2) {
            float a0 = 0.f, a1 = 0.f;
            #pragma unroll
            for (int q = 0; q < 4; ++q) {
                const float4 xv0 = *reinterpret_cast<const float4*>(
                    p.xbuf + r * DIMK + kbase + q * 4);
                const float4 xv1 = *reinterpret_cast<const float4*>(
                    p.xbuf + (r + 1) * DIMK + kbase + q * 4);
                a0 = fmaf(xv0.x, Wreg[q * 4 + 0], a0);
                a1 = fmaf(xv1.x, Wreg[q * 4 + 0], a1);
                a0 = fmaf(xv0.y, Wreg[q * 4 + 1], a0);
                a1 = fmaf(xv1.y, Wreg[q * 4 + 1], a1);
                a0 = fmaf(xv0.z, Wreg[q * 4 + 2], a0);
                a1 = fmaf(xv1.z, Wreg[q * 4 + 2], a1);
                a0 = fmaf(xv0.w, Wreg[q * 4 + 3], a0);
                a1 = fmaf(xv1.w, Wreg[q * 4 + 3], a1);
            }
            a0 += __shfl_xor_sync(0xffffffffu, a0, 8);
            a1 += __shfl_xor_sync(0xffffffffu, a1, 8);
            a0 += __shfl_xor_sync(0xffffffffu, a0, 16);
            a1 += __shfl_xor_sync(0xffffffffu, a1, 16);
            if (kh0) {
                x1acc = fmaf(p.attn0[r],     fsigmoid(a0 + b0c), x1acc);
                x1acc = fmaf(p.attn0[r + 1], fsigmoid(a1 + b0c), x1acc);
            }
        }
        float a16 = 0.f;
        #pragma unroll
        for (int q = 0; q < 4; ++q) {
            const float4 xv = *reinterpret_cast<const float4*>(p.x0 + kbase + q * 4);
            a16 = fmaf(xv.x, Wreg[q * 4 + 0], a16);
            a16 = fmaf(xv.y, Wreg[q * 4 + 1], a16);
            a16 = fmaf(xv.z, Wreg[q * 4 + 2], a16);
            a16 = fmaf(xv.w, Wreg[q * 4 + 3], a16);
        }
        a16 += __shfl_xor_sync(0xffffffffu, a16, 8);
        a16 += __shfl_xor_sync(0xffffffffu, a16, 16);
        if (kh0) p.x1[c] = x1acc + fsigmoid(a16 + b0c);
    }
    __syncthreads();

    // ---- P5: final GEMM (W1 via L1-cached ldg) + tanh (all items) ----
    #pragma unroll
    for (int ii = 0; ii < NITEMS; ++ii) {
        PerItem& p = s.pi[ii];
        float acc = 0.f;
        #pragma unroll
        for (int kk = 0; kk < 16; ++kk) {
            const int k = kbase + kk;
            acc = fmaf(p.x1[k], __ldg(W1g + k * DIMK + c), acc);
        }
        acc += __shfl_xor_sync(0xffffffffu, acc, 8);
        acc += __shfl_xor_sync(0xffffffffu, acc, 16);
        if (kh0) p.outf[c] = tanhf(acc + s.b1[c]);
    }
    __syncthreads();

    // ---- P6: sigmoid(user . item), one warp per item ----
    if (warp < NITEMS) {
        PerItem& p = s.pi[warp];
        float pp = p.userv[lane] * p.outf[lane] + p.userv[lane + 32] * p.outf[lane + 32];
        #pragma unroll
        for (int off = 16; off > 0; off >>= 1)
            pp += __shfl_xor_sync(0xffffffffu, pp, off);
        if (lane == 0) out[item0 + warp] = fsigmoid(pp);
    }
}

extern "C" void kernel_launch(void* const* d_in, const int* in_sizes, int n_in,
                              void* d_out, int out_size) {
    const int*   u       = (const int*)d_in[0];
    const int*   v       = (const int*)d_in[1];
    const int*   adj     = (const int*)d_in[2];
    const int*   rel_adj = (const int*)d_in[3];
    const float* usr_emb = (const float*)d_in[4];
    const float* ent_emb = (const float*)d_in[5];
    const float* rel_emb = (const float*)d_in[6];
    const float* W0      = (const float*)d_in[7];
    const float* b0      = (const float*)d_in[8];
    const float* W1      = (const float*)d_in[9];
    const float* b1      = (const float*)d_in[10];
    float* outp = (float*)d_out;

    const int smem = (int)sizeof(Smem);
    cudaFuncSetAttribute(kgnn_kernel, cudaFuncAttributeMaxDynamicSharedMemorySize, smem);
    kgnn_kernel<<<GRID, NT, smem>>>(u, v, adj, rel_adj, usr_emb, ent_emb, rel_emb,
                                    W0, b0, W1, b1, outp);
}

// round 8
// speedup vs baseline: 1.1457x; 1.1457x over previous
#include <cuda_runtime.h>
#include <math.h>

#define DIMK 64
#define NN 16
#define BATCH 4096
#define NRELS 33
#define NT 256
#define NITEMS 2
#define GRID (BATCH / NITEMS)

struct PerItem {
    float xbuf[NN * DIMK];    // 4 KB
    float userv[DIMK];
    float x0[DIMK];
    float x1[DIMK];
    float outf[DIMK];
    float attn[NN * NN];      // 1 KB
    float urel[NRELS + 3];
    float attn0[NN];
    int   e1[NN];
    int   e2[NN * NN];        // 1 KB
    int   r2[NN * NN];        // 1 KB
    int   r1[NN];
};

struct Smem {
    PerItem pi[NITEMS];
    float b0[DIMK];
    float b1[DIMK];
};

__device__ __forceinline__ float fsigmoid(float x) {
    return __fdividef(1.0f, 1.0f + __expf(-x));
}

__global__ __launch_bounds__(NT, 6)
void kgnn_kernel(const int* __restrict__ u, const int* __restrict__ v,
                 const int* __restrict__ adj, const int* __restrict__ rel_adj,
                 const float* __restrict__ usr_emb, const float* __restrict__ ent_emb,
                 const float* __restrict__ rel_emb,
                 const float* __restrict__ W0g, const float* __restrict__ b0g,
                 const float* __restrict__ W1g, const float* __restrict__ b1g,
                 float* __restrict__ out)
{
    extern __shared__ char smem_raw[];
    Smem& s = *reinterpret_cast<Smem*>(smem_raw);
    const int tid  = threadIdx.x;
    const int lane = tid & 31;
    const int warp = tid >> 5;
    const int c     = warp * 8 + (lane & 7);  // output column 0..63
    const int kh    = lane >> 3;              // k-quarter 0..3
    const int kbase = kh * 16;
    const bool kh0  = (kh == 0);

    const float4* ent4 = reinterpret_cast<const float4*>(ent_emb);
    const int item0 = blockIdx.x * NITEMS;

    // W0 column-slice in registers, once per CTA
    float Wreg[16];
    #pragma unroll
    for (int kk = 0; kk < 16; ++kk)
        Wreg[kk] = __ldg(W0g + (kbase + kk) * DIMK + c);
    if (tid < DIMK) { s.b0[tid] = b0g[tid]; s.b1[tid] = b1g[tid]; }
    __syncthreads();

    // ---- P1: indices + root vectors + urel (both items) ----
    #pragma unroll
    for (int ii = 0; ii < NITEMS; ++ii) {
        PerItem& p = s.pi[ii];
        const int vv = __ldg(v + item0 + ii);
        const int uu = __ldg(u + item0 + ii);
        const int m = tid >> 4, n = tid & 15;
        const int e1m = __ldg(adj + vv * NN + m);
        p.e2[tid] = __ldg(adj + e1m * NN + n);
        p.r2[tid] = __ldg(rel_adj + e1m * NN + n);
        if (n == 0) p.e1[m] = e1m;
        if (tid < 16) {
            p.r1[tid] = __ldg(rel_adj + vv * NN + tid);
            reinterpret_cast<float4*>(p.userv)[tid] = __ldg(
                reinterpret_cast<const float4*>(usr_emb) + uu * 16 + tid);
        }
        const float ua = __ldg(usr_emb + uu * DIMK + lane);
        const float ub = __ldg(usr_emb + uu * DIMK + lane + 32);
        for (int r = warp; r < NRELS; r += 8) {
            float pp = ua * __ldg(rel_emb + r * DIMK + lane)
                     + ub * __ldg(rel_emb + r * DIMK + lane + 32);
            #pragma unroll
            for (int off = 16; off > 0; off >>= 1)
                pp += __shfl_xor_sync(0xffffffffu, pp, off);
            if (lane == 0) p.urel[r] = pp;
        }
    }
    __syncthreads();

    // ---- P2: softmax via half-warp butterflies (both items) ----
    #pragma unroll
    for (int ii = 0; ii < NITEMS; ++ii) {
        PerItem& p = s.pi[ii];
        float sc = p.urel[p.r2[tid]];
        float mx = sc;
        #pragma unroll
        for (int off = 8; off > 0; off >>= 1)
            mx = fmaxf(mx, __shfl_xor_sync(0xffffffffu, mx, off));
        float e = __expf(sc - mx);
        float sum = e;
        #pragma unroll
        for (int off = 8; off > 0; off >>= 1)
            sum += __shfl_xor_sync(0xffffffffu, sum, off);
        p.attn[tid] = __fdividef(e, sum);

        if (warp == ii) {   // hop-0 softmax on warp ii
            float sc0 = p.urel[p.r1[lane & 15]];
            float m0 = sc0;
            #pragma unroll
            for (int off = 8; off > 0; off >>= 1)
                m0 = fmaxf(m0, __shfl_xor_sync(0xffffffffu, m0, off));
            float e0 = __expf(sc0 - m0);
            float s0 = e0;
            #pragma unroll
            for (int off = 8; off > 0; off >>= 1)
                s0 += __shfl_xor_sync(0xffffffffu, s0, off);
            if (lane < 16) p.attn0[lane] = __fdividef(e0, s0);
        }
    }
    __syncthreads();

    // ---- P3: hop-1 aggregation (both items) + x0 on warps 6/7 ----
    #pragma unroll
    for (int ii = 0; ii < NITEMS; ++ii) {
        PerItem& p = s.pi[ii];
        const int m  = warp * 2 + (lane >> 4);
        const int l4 = lane & 15;
        const int4*   e2v = reinterpret_cast<const int4*>(p.e2 + m * NN);
        const float4* av  = reinterpret_cast<const float4*>(p.attn + m * NN);
        float4 acc = __ldg(ent4 + p.e1[m] * 16 + l4);   // self vector
        #pragma unroll
        for (int j = 0; j < 4; ++j) {
            const int4   ei = e2v[j];
            const float4 aw = av[j];
            const float4 v0 = __ldg(ent4 + ei.x * 16 + l4);
            const float4 v1 = __ldg(ent4 + ei.y * 16 + l4);
            const float4 v2 = __ldg(ent4 + ei.z * 16 + l4);
            const float4 v3 = __ldg(ent4 + ei.w * 16 + l4);
            acc.x = fmaf(aw.x, v0.x, acc.x); acc.y = fmaf(aw.x, v0.y, acc.y);
            acc.z = fmaf(aw.x, v0.z, acc.z); acc.w = fmaf(aw.x, v0.w, acc.w);
            acc.x = fmaf(aw.y, v1.x, acc.x); acc.y = fmaf(aw.y, v1.y, acc.y);
            acc.z = fmaf(aw.y, v1.z, acc.z); acc.w = fmaf(aw.y, v1.w, acc.w);
            acc.x = fmaf(aw.z, v2.x, acc.x); acc.y = fmaf(aw.z, v2.y, acc.y);
            acc.z = fmaf(aw.z, v2.z, acc.z); acc.w = fmaf(aw.z, v2.w, acc.w);
            acc.x = fmaf(aw.w, v3.x, acc.x); acc.y = fmaf(aw.w, v3.y, acc.y);
            acc.z = fmaf(aw.w, v3.z, acc.z); acc.w = fmaf(aw.w, v3.w, acc.w);
        }
        reinterpret_cast<float4*>(p.xbuf + m * DIMK)[l4] = acc;

        if (warp == 6 + ii && lane < 16) {   // x0 aggregation, one warp per item
            const int vv = __ldg(v + item0 + ii);
            float4 a0 = __ldg(ent4 + vv * 16 + lane);
            #pragma unroll
            for (int n = 0; n < NN; ++n) {
                const float4 ev = __ldg(ent4 + p.e1[n] * 16 + lane);
                const float  an = p.attn0[n];
                a0.x = fmaf(an, ev.x, a0.x);
                a0.y = fmaf(an, ev.y, a0.y);
                a0.z = fmaf(an, ev.z, a0.z);
                a0.w = fmaf(an, ev.w, a0.w);
            }
            reinterpret_cast<float4*>(p.x0)[lane] = a0;
        }
    }
    __syncthreads();

    // ---- P4: fused GEMM (both items; h1 stays in registers) ----
    #pragma unroll
    for (int ii = 0; ii < NITEMS; ++ii) {
        PerItem& p = s.pi[ii];
        const float b0c = s.b0[c];
        float x1acc = 0.f;
        #pragma unroll
        for (int r = 0; r < NN; r += 2) {
            float a0 = 0.f, a1 = 0.f;
            #pragma unroll
            for (int q = 0; q < 4; ++q) {
                const float4 xv0 = *reinterpret_cast<const float4*>(
                    p.xbuf + r * DIMK + kbase + q * 4);
                const float4 xv1 = *reinterpret_cast<const float4*>(
                    p.xbuf + (r + 1) * DIMK + kbase + q * 4);
                a0 = fmaf(xv0.x, Wreg[q * 4 + 0], a0);
                a1 = fmaf(xv1.x, Wreg[q * 4 + 0], a1);
                a0 = fmaf(xv0.y, Wreg[q * 4 + 1], a0);
                a1 = fmaf(xv1.y, Wreg[q * 4 + 1], a1);
                a0 = fmaf(xv0.z, Wreg[q * 4 + 2], a0);
                a1 = fmaf(xv1.z, Wreg[q * 4 + 2], a1);
                a0 = fmaf(xv0.w, Wreg[q * 4 + 3], a0);
                a1 = fmaf(xv1.w, Wreg[q * 4 + 3], a1);
            }
            a0 += __shfl_xor_sync(0xffffffffu, a0, 8);
            a1 += __shfl_xor_sync(0xffffffffu, a1, 8);
            a0 += __shfl_xor_sync(0xffffffffu, a0, 16);
            a1 += __shfl_xor_sync(0xffffffffu, a1, 16);
            if (kh0) {
                x1acc = fmaf(p.attn0[r],     fsigmoid(a0 + b0c), x1acc);
                x1acc = fmaf(p.attn0[r + 1], fsigmoid(a1 + b0c), x1acc);
            }
        }
        float a16 = 0.f;
        #pragma unroll
        for (int q = 0; q < 4; ++q) {
            const float4 xv = *reinterpret_cast<const float4*>(p.x0 + kbase + q * 4);
            a16 = fmaf(xv.x, Wreg[q * 4 + 0], a16);
            a16 = fmaf(xv.y, Wreg[q * 4 + 1], a16);
            a16 = fmaf(xv.z, Wreg[q * 4 + 2], a16);
            a16 = fmaf(xv.w, Wreg[q * 4 + 3], a16);
        }
        a16 += __shfl_xor_sync(0xffffffffu, a16, 8);
        a16 += __shfl_xor_sync(0xffffffffu, a16, 16);
        if (kh0) p.x1[c] = x1acc + fsigmoid(a16 + b0c);
    }
    __syncthreads();

    // ---- P5: final GEMM (W1 via L1-cached ldg) + tanh (both items) ----
    #pragma unroll
    for (int ii = 0; ii < NITEMS; ++ii) {
        PerItem& p = s.pi[ii];
        float acc = 0.f;
        #pragma unroll
        for (int kk = 0; kk < 16; ++kk) {
            const int k = kbase + kk;
            acc = fmaf(p.x1[k], __ldg(W1g + k * DIMK + c), acc);
        }
        acc += __shfl_xor_sync(0xffffffffu, acc, 8);
        acc += __shfl_xor_sync(0xffffffffu, acc, 16);
        if (kh0) p.outf[c] = tanhf(acc + s.b1[c]);
    }
    __syncthreads();

    // ---- P6: sigmoid(user . item), one warp per item ----
    if (warp < NITEMS) {
        PerItem& p = s.pi[warp];
        float pp = p.userv[lane] * p.outf[lane] + p.userv[lane + 32] * p.outf[lane + 32];
        #pragma unroll
        for (int off = 16; off > 0; off >>= 1)
            pp += __shfl_xor_sync(0xffffffffu, pp, off);
        if (lane == 0) out[item0 + warp] = fsigmoid(pp);
    }
}

extern "C" void kernel_launch(void* const* d_in, const int* in_sizes, int n_in,
                              void* d_out, int out_size) {
    const int*   u       = (const int*)d_in[0];
    const int*   v       = (const int*)d_in[1];
    const int*   adj     = (const int*)d_in[2];
    const int*   rel_adj = (const int*)d_in[3];
    const float* usr_emb = (const float*)d_in[4];
    const float* ent_emb = (const float*)d_in[5];
    const float* rel_emb = (const float*)d_in[6];
    const float* W0      = (const float*)d_in[7];
    const float* b0      = (const float*)d_in[8];
    const float* W1      = (const float*)d_in[9];
    const float* b1      = (const float*)d_in[10];
    float* outp = (float*)d_out;

    const int smem = (int)sizeof(Smem);
    cudaFuncSetAttribute(kgnn_kernel, cudaFuncAttributeMaxDynamicSharedMemorySize, smem);
    kgnn_kernel<<<GRID, NT, smem>>>(u, v, adj, rel_adj, usr_emb, ent_emb, rel_emb,
                                    W0, b0, W1, b1, outp);
}